// round 1
// baseline (speedup 1.0000x reference)
#include <cuda_runtime.h>
#include <math.h>

#define Bb 32
#define Nn 512
#define Ee 2048
#define Dd 128
#define NSTEP 3

// ---------------- scratch (device globals: allocation-free) ----------------
__device__ float g_edge0[Bb*Ee*Dd];
__device__ float g_edge1[Bb*Ee*Dd];
__device__ float g_prop0[Bb*Nn*Dd];
__device__ float g_prop1[Bb*Nn*Dd];
__device__ float g_acat [Bb*Nn*2*Dd];
__device__ float g_r    [Bb*Nn*Dd];
__device__ float g_z    [Bb*Nn*Dd];
__device__ float g_hhat [Bb*Nn*Dd];
__device__ float g_t1   [Bb*Nn*Dd];
__device__ float g_outn [Bb*Nn*Dd];
__device__ float g_att  [Bb*Nn];
__device__ float g_aw   [Bb*Nn];
__device__ float g_part [Bb*20*Dd];
__device__ float g_zero_bias[Dd];   // zero-initialized by CUDA (.bss)

// ---------------- tiled SGEMM, N fixed = 128, fused bias + activation ------
// C[M,128] = act(A[M,K] @ W[K,128] + bias)   row-major, arbitrary ld/stride.
// BM=64 BN=128 BK=16, 256 threads, 4x8 microtile. ACT: 0=none 1=sigmoid 2=tanh
template<int ACT>
__global__ __launch_bounds__(256)
void gemm_bias_act(const float* __restrict__ A, int lda, long long sA,
                   const float* __restrict__ Wm, int ldb, long long sB,
                   const float* __restrict__ bias,
                   float* __restrict__ C, int ldc, long long sC,
                   int K)
{
    const int BM = 64, BK = 16;
    __shared__ float As[BK][BM + 4];
    __shared__ float Bs[BK][128];

    const long long b = blockIdx.z;
    A  += b * sA;
    Wm += b * sB;
    C  += b * sC;

    const int m0  = blockIdx.y * BM;
    const int tid = threadIdx.x;
    const int tx  = tid & 15;
    const int ty  = tid >> 4;

    const int lm  = tid >> 2;
    const int lk  = (tid & 3) * 4;
    const int lbk = tid >> 4;
    const int lbn = (tid & 15) * 8;

    float acc[4][8];
#pragma unroll
    for (int i = 0; i < 4; i++)
#pragma unroll
        for (int j = 0; j < 8; j++) acc[i][j] = 0.f;

    for (int k0 = 0; k0 < K; k0 += BK) {
        float4 av = *(const float4*)&A[(long long)(m0 + lm) * lda + k0 + lk];
        As[lk + 0][lm] = av.x;
        As[lk + 1][lm] = av.y;
        As[lk + 2][lm] = av.z;
        As[lk + 3][lm] = av.w;
        float4 bv0 = *(const float4*)&Wm[(long long)(k0 + lbk) * ldb + lbn];
        float4 bv1 = *(const float4*)&Wm[(long long)(k0 + lbk) * ldb + lbn + 4];
        *(float4*)&Bs[lbk][lbn]     = bv0;
        *(float4*)&Bs[lbk][lbn + 4] = bv1;
        __syncthreads();

#pragma unroll
        for (int kk = 0; kk < BK; kk++) {
            float a[4], w[8];
#pragma unroll
            for (int i = 0; i < 4; i++) a[i] = As[kk][ty * 4 + i];
#pragma unroll
            for (int j = 0; j < 8; j++) w[j] = Bs[kk][tx + 16 * j];
#pragma unroll
            for (int i = 0; i < 4; i++)
#pragma unroll
                for (int j = 0; j < 8; j++)
                    acc[i][j] = fmaf(a[i], w[j], acc[i][j]);
        }
        __syncthreads();
    }

#pragma unroll
    for (int i = 0; i < 4; i++) {
        const long long m = m0 + ty * 4 + i;
#pragma unroll
        for (int j = 0; j < 8; j++) {
            const int n = tx + 16 * j;
            float v = acc[i][j] + bias[n];
            if (ACT == 1)      v = 1.f / (1.f + __expf(-v));
            else if (ACT == 2) v = tanhf(v);
            C[m * ldc + n] = v;
        }
    }
}

// ---------------- elementwise helpers --------------------------------------
__global__ void k_prop_to_cat(const float* __restrict__ prop, float* __restrict__ acat) {
    const int idx = blockIdx.x * blockDim.x + threadIdx.x;
    const int r = idx >> 7, c = idx & 127;
    acat[(long long)r * 256 + 128 + c] = prop[idx];
}

__global__ void k_rprop_to_cat(const float* __restrict__ rg, const float* __restrict__ prop,
                               float* __restrict__ acat) {
    const int idx = blockIdx.x * blockDim.x + threadIdx.x;
    const int r = idx >> 7, c = idx & 127;
    acat[(long long)r * 256 + 128 + c] = rg[idx] * prop[idx];
}

__global__ void k_update_prop(const float* __restrict__ z, const float* __restrict__ h,
                              const float* __restrict__ p, float* __restrict__ pn) {
    const int idx = blockIdx.x * blockDim.x + threadIdx.x;
    const float zz = z[idx];
    pn[idx] = (1.f - zz) * p[idx] + zz * h[idx];
}

__global__ void k_att_score(const float* __restrict__ t1, const float* __restrict__ W2,
                            const float* __restrict__ b2, float* __restrict__ att) {
    const int warp = (blockIdx.x * blockDim.x + threadIdx.x) >> 5;
    const int lane = threadIdx.x & 31;
    if (warp >= Bb * Nn) return;
    const float* row = t1 + (long long)warp * Dd;
    float s = 0.f;
#pragma unroll
    for (int c = lane; c < Dd; c += 32) s = fmaf(row[c], W2[c], s);
#pragma unroll
    for (int o = 16; o; o >>= 1) s += __shfl_xor_sync(0xffffffffu, s, o);
    if (lane == 0) att[warp] = s + b2[0];
}

__global__ void k_softmax(const float* __restrict__ att, float* __restrict__ aw) {
    const int b = blockIdx.x;
    const int n = threadIdx.x;              // 512
    __shared__ float red[Nn];
    const float v = att[b * Nn + n];
    red[n] = v;
    __syncthreads();
    for (int s = 256; s; s >>= 1) { if (n < s) red[n] = fmaxf(red[n], red[n + s]); __syncthreads(); }
    const float m = red[0];
    __syncthreads();
    const float e = __expf(v - m);
    red[n] = e;
    __syncthreads();
    for (int s = 256; s; s >>= 1) { if (n < s) red[n] += red[n + s]; __syncthreads(); }
    aw[b * Nn + n] = e / red[0];
}

__global__ void k_residual_part(const float* __restrict__ prop0, const float* __restrict__ edge0,
                                float* __restrict__ part) {
    const int ch = blockIdx.x;   // 0..19, 128 rows each
    const int b  = blockIdx.y;
    const int d  = threadIdx.x;  // 128
    float s = 0.f;
    const int r0 = ch * 128;
#pragma unroll 4
    for (int r = r0; r < r0 + 128; r++) {
        if (r < Nn) s += prop0[((long long)b * Nn + r) * Dd + d];
        else        s += edge0[((long long)b * Ee + (r - Nn)) * Dd + d];
    }
    part[(b * 20 + ch) * Dd + d] = s;
}

__global__ void k_final(const float* __restrict__ aw, const float* __restrict__ outn,
                        const float* __restrict__ part,
                        float* __restrict__ d_res, float* __restrict__ d_mul) {
    const int b = blockIdx.x;
    const int d = threadIdx.x;   // 128
    __shared__ float saw[Nn];
    for (int n = threadIdx.x; n < Nn; n += 128) saw[n] = aw[b * Nn + n];
    __syncthreads();
    const float* ob = outn + (long long)b * Nn * Dd;
    float acc = 0.f;
#pragma unroll 8
    for (int n = 0; n < Nn; n++) acc = fmaf(saw[n], ob[n * Dd + d], acc);
    float resid = 0.f;
#pragma unroll
    for (int c = 0; c < 20; c++) resid += part[(b * 20 + c) * Dd + d];
    resid *= (1.f / 2560.f);
    d_mul[b * Dd + d] = acc;
    d_res[b * Dd + d] = fmaxf(tanhf(acc) + resid, 0.f);
}

// ---------------- host launch ----------------------------------------------
static float* sym(const void* s) { void* p = nullptr; cudaGetSymbolAddress(&p, s); return (float*)p; }

extern "C" void kernel_launch(void* const* d_in, const int* in_sizes, int n_in,
                              void* d_out, int out_size) {
    const float* prop_in = (const float*)d_in[0];
    const float* edge_in = (const float*)d_in[1];
    const float* Amat    = (const float*)d_in[2];
    const float* link_W  = (const float*)d_in[4];
    const float* link_b  = (const float*)d_in[5];
    const float* reset_W = (const float*)d_in[6];
    const float* reset_b = (const float*)d_in[7];
    const float* upd_W   = (const float*)d_in[8];
    const float* upd_b   = (const float*)d_in[9];
    const float* trans_W = (const float*)d_in[10];
    const float* trans_b = (const float*)d_in[11];
    const float* att_W1  = (const float*)d_in[12];
    const float* att_b1  = (const float*)d_in[13];
    const float* att_W2  = (const float*)d_in[14];
    const float* att_b2  = (const float*)d_in[15];
    const float* out_W   = (const float*)d_in[16];
    const float* out_b   = (const float*)d_in[17];

    float* out      = (float*)d_out;
    float* out_res  = out;
    float* out_mul  = out + Bb * Dd;
    float* out_edge = out + 2 * Bb * Dd;

    float* edge0 = sym(g_edge0); float* edge1 = sym(g_edge1);
    float* prop0 = sym(g_prop0); float* prop1 = sym(g_prop1);
    float* acat  = sym(g_acat);
    float* rg = sym(g_r); float* zg = sym(g_z); float* hh = sym(g_hhat);
    float* t1 = sym(g_t1); float* outn = sym(g_outn);
    float* att = sym(g_att); float* aw = sym(g_aw); float* part = sym(g_part);
    float* zbias = sym(g_zero_bias);

    const int elems   = Bb * Nn * Dd;
    const int EW_BLK  = 256, EW_GRID = elems / EW_BLK;

    const float* e_in[NSTEP]  = { edge_in, edge0, edge1 };
    float*       e_out[NSTEP] = { edge0,  edge1,  out_edge };
    const float* p_in[NSTEP]  = { prop_in, prop0, prop1 };
    float*       p_out[NSTEP] = { prop0,  prop1,  prop0 };

    for (int s = 0; s < NSTEP; s++) {
        // edge = edge @ link_W + link_b
        gemm_bias_act<0><<<dim3(1, (Bb * Ee) / 64, 1), 256>>>(
            e_in[s], Dd, 0, link_W, Dd, 0, link_b, e_out[s], Dd, 0, Dd);
        // a_cur = A @ edge  (batched) -> acat[:, 0:128]
        gemm_bias_act<0><<<dim3(1, Nn / 64, Bb), 256>>>(
            Amat, Ee, (long long)Nn * Ee,
            e_out[s], Dd, (long long)Ee * Dd,
            zbias, acat, 2 * Dd, (long long)Nn * 2 * Dd, Ee);
        // acat[:, 128:256] = prop
        k_prop_to_cat<<<EW_GRID, EW_BLK>>>(p_in[s], acat);
        // r, z
        gemm_bias_act<1><<<dim3(1, (Bb * Nn) / 64, 1), 256>>>(
            acat, 2 * Dd, 0, reset_W, Dd, 0, reset_b, rg, Dd, 0, 2 * Dd);
        gemm_bias_act<1><<<dim3(1, (Bb * Nn) / 64, 1), 256>>>(
            acat, 2 * Dd, 0, upd_W, Dd, 0, upd_b, zg, Dd, 0, 2 * Dd);
        // acat[:, 128:256] = r * prop
        k_rprop_to_cat<<<EW_GRID, EW_BLK>>>(rg, p_in[s], acat);
        // h_hat
        gemm_bias_act<2><<<dim3(1, (Bb * Nn) / 64, 1), 256>>>(
            acat, 2 * Dd, 0, trans_W, Dd, 0, trans_b, hh, Dd, 0, 2 * Dd);
        // prop update
        k_update_prop<<<EW_GRID, EW_BLK>>>(zg, hh, p_in[s], p_out[s]);
    }

    // epilogue
    gemm_bias_act<2><<<dim3(1, (Bb * Nn) / 64, 1), 256>>>(
        prop0, Dd, 0, att_W1, Dd, 0, att_b1, t1, Dd, 0, Dd);
    k_att_score<<<(Bb * Nn) / 8, 256>>>(t1, att_W2, att_b2, att);
    k_softmax<<<Bb, Nn>>>(att, aw);
    gemm_bias_act<2><<<dim3(1, (Bb * Nn) / 64, 1), 256>>>(
        prop0, Dd, 0, out_W, Dd, 0, out_b, outn, Dd, 0, Dd);
    k_residual_part<<<dim3(20, Bb), Dd>>>(prop_in, edge_in, part);
    k_final<<<Bb, Dd>>>(aw, outn, part, out_res, out_mul);
}

// round 2
// speedup vs baseline: 3.1369x; 3.1369x over previous
#include <cuda_runtime.h>
#include <math.h>
#include <stdint.h>

#define Bb 32
#define Nn 512
#define Ee 2048
#define Dd 128
#define NSTEP 3
#define MROWS (Bb*Nn)          // 16384

// ---------------- scratch (device globals: allocation-free) ----------------
__device__ float g_acat1[MROWS*256];        // [F/a_cur | prop]
__device__ float g_acat2[MROWS*256];        // [a_cur   | r*prop]
__device__ float g_zbuf [MROWS*Dd];
__device__ float g_t1   [MROWS*Dd];
__device__ float g_outn [MROWS*Dd];
__device__ float g_split[2*MROWS*Dd];       // F_init split-K partials
__device__ float g_rA   [MROWS];
__device__ float g_Wrz  [256*256];
__device__ float g_brz  [256];
__device__ float g_W2   [Dd*Dd];
__device__ float g_W3   [Dd*Dd];
__device__ float g_beff [Dd];
__device__ float g_att  [Bb*Nn];
__device__ float g_aw   [Bb*Nn];
__device__ float g_part [Bb*20*Dd];

// ---------------- tf32 helpers ---------------------------------------------
__device__ __forceinline__ uint32_t f2tf32(float x) {
    uint32_t u;
    asm("cvt.rna.tf32.f32 %0, %1;" : "=r"(u) : "f"(x));
    return u;
}
__device__ __forceinline__ void mma_tf32(float* c, const uint32_t* a, const uint32_t* b) {
    asm volatile("mma.sync.aligned.m16n8k8.row.col.f32.tf32.tf32.f32 "
                 "{%0,%1,%2,%3},{%4,%5,%6,%7},{%8,%9},{%0,%1,%2,%3};"
                 : "+f"(c[0]), "+f"(c[1]), "+f"(c[2]), "+f"(c[3])
                 : "r"(a[0]), "r"(a[1]), "r"(a[2]), "r"(a[3]),
                   "r"(b[0]), "r"(b[1]));
}

// ---------------- tf32 GEMM: C[M x (gridDim.x*128)] = epi(A[M,K] @ W[K,N]) --
// BM=128 BN=128 BK=32, 256 threads (8 warps, 2x4). Row-major A and W.
// EPI: 0=splitK plain (blockIdx.x = k-split)   1=+bias
//      2=ACUR (+rA[r]*bias, dual store C,C2)   3=RZ sigmoid (r*prop / z split)
//      4=HHAT tanh + GRU blend                 5=tanh(+bias)
template<int EPI>
__global__ __launch_bounds__(256)
void gemm_tf32(const float* __restrict__ A, int lda, long long sA,
               const float* __restrict__ W, int ldb, long long sB,
               const float* __restrict__ bias,
               float* __restrict__ C, int ldc, long long sC, long long sCx,
               float* __restrict__ C2,
               const float* __restrict__ aux1,   // rA (EPI2) / zbuf (EPI4)
               const float* __restrict__ aux2,   // acat1 (EPI3) / prop (EPI4)
               int Klen)
{
    __shared__ uint32_t As[128][36];   // [m][k]
    __shared__ uint32_t Bs[32][136];   // [k][n]

    const int tid  = threadIdx.x;
    const int warp = tid >> 5, lane = tid & 31;
    const int wm = warp & 1, wn = warp >> 1;          // warp tile (wm*64, wn*32)
    const int group = lane >> 2, tig = lane & 3;

    const int  n0g  = (EPI == 0) ? 0 : blockIdx.x * 128;
    const int  kOff = (EPI == 0) ? blockIdx.x * Klen : 0;
    const int  m0   = blockIdx.y * 128;
    const long long bz = blockIdx.z;
    A += bz * sA;
    W += bz * sB;
    C += bz * sC + ((EPI == 0) ? blockIdx.x * sCx : 0ll);

    float acc[4][4][4];
#pragma unroll
    for (int i = 0; i < 4; i++)
#pragma unroll
        for (int j = 0; j < 4; j++)
#pragma unroll
            for (int q = 0; q < 4; q++) acc[i][j][q] = 0.f;

    const int ar  = tid >> 1, acb = (tid & 1) * 16;   // A loader: row, col-base
    const int bkr = tid >> 3, bcb = (tid & 7) * 16;   // B loader

    for (int k0 = 0; k0 < Klen; k0 += 32) {
        const float* asrc = A + (long long)(m0 + ar) * lda + kOff + k0 + acb;
#pragma unroll
        for (int i = 0; i < 4; i++) {
            float4 v = *(const float4*)(asrc + 4 * i);
            As[ar][acb + 4 * i + 0] = f2tf32(v.x);
            As[ar][acb + 4 * i + 1] = f2tf32(v.y);
            As[ar][acb + 4 * i + 2] = f2tf32(v.z);
            As[ar][acb + 4 * i + 3] = f2tf32(v.w);
        }
        const float* bsrc = W + (long long)(kOff + k0 + bkr) * ldb + n0g + bcb;
#pragma unroll
        for (int i = 0; i < 4; i++) {
            float4 v = *(const float4*)(bsrc + 4 * i);
            Bs[bkr][bcb + 4 * i + 0] = f2tf32(v.x);
            Bs[bkr][bcb + 4 * i + 1] = f2tf32(v.y);
            Bs[bkr][bcb + 4 * i + 2] = f2tf32(v.z);
            Bs[bkr][bcb + 4 * i + 3] = f2tf32(v.w);
        }
        __syncthreads();

#pragma unroll
        for (int k8 = 0; k8 < 4; k8++) {
            const int kb = k8 * 8;
            uint32_t af[4][4], bf[4][2];
#pragma unroll
            for (int mi = 0; mi < 4; mi++) {
                const int m = wm * 64 + mi * 16;
                af[mi][0] = As[m + group][kb + tig];
                af[mi][1] = As[m + group + 8][kb + tig];
                af[mi][2] = As[m + group][kb + tig + 4];
                af[mi][3] = As[m + group + 8][kb + tig + 4];
            }
#pragma unroll
            for (int ni = 0; ni < 4; ni++) {
                const int n = wn * 32 + ni * 8;
                bf[ni][0] = Bs[kb + tig][n + group];
                bf[ni][1] = Bs[kb + tig + 4][n + group];
            }
#pragma unroll
            for (int mi = 0; mi < 4; mi++)
#pragma unroll
                for (int ni = 0; ni < 4; ni++)
                    mma_tf32(acc[mi][ni], af[mi], bf[ni]);
        }
        __syncthreads();
    }

    // ---- epilogue ----
#pragma unroll
    for (int mi = 0; mi < 4; mi++) {
        const int rb = m0 + wm * 64 + mi * 16 + group;
#pragma unroll
        for (int ni = 0; ni < 4; ni++) {
            const int cl = wn * 32 + ni * 8 + 2 * tig;   // local col in tile
#pragma unroll
            for (int rr = 0; rr < 2; rr++) {
                const int r = rb + rr * 8;
#pragma unroll
                for (int cc = 0; cc < 2; cc++) {
                    float v = acc[mi][ni][rr * 2 + cc];
                    const int col  = cl + cc;       // 0..127
                    const int gcol = n0g + col;     // global col
                    if (EPI == 0) {
                        C[(long long)r * ldc + col] = v;
                    } else if (EPI == 1) {
                        C[(long long)r * ldc + col] = v + bias[col];
                    } else if (EPI == 2) {
                        v += aux1[r] * bias[col];
                        C [(long long)r * 256 + col] = v;
                        C2[(long long)r * 256 + col] = v;
                    } else if (EPI == 3) {
                        v = 1.f / (1.f + __expf(-(v + bias[gcol])));
                        if (gcol < 128)
                            C2[(long long)r * 256 + 128 + gcol] =
                                v * aux2[(long long)r * 256 + 128 + gcol];
                        else
                            C[(long long)r * 128 + (gcol - 128)] = v;
                    } else if (EPI == 4) {
                        const float h = tanhf(v + bias[col]);
                        const float z = aux1[(long long)r * 128 + col];
                        const float p = aux2[(long long)r * 256 + col];
                        C[(long long)r * 256 + col] = (1.f - z) * p + z * h;
                    } else { // 5
                        C[(long long)r * ldc + col] = tanhf(v + bias[col]);
                    }
                }
            }
        }
    }
}

// ---------------- small helper kernels --------------------------------------
__global__ void k_rowsumA(const float* __restrict__ A, float* __restrict__ rA) {
    const int row  = blockIdx.x * 8 + (threadIdx.x >> 5);
    const int lane = threadIdx.x & 31;
    const float4* p = (const float4*)(A + (long long)row * Ee);
    float s = 0.f;
#pragma unroll
    for (int i = lane; i < Ee / 4; i += 32) {
        float4 v = p[i];
        s += (v.x + v.y) + (v.z + v.w);
    }
#pragma unroll
    for (int o = 16; o; o >>= 1) s += __shfl_xor_sync(0xffffffffu, s, o);
    if (lane == 0) rA[row] = s;
}

__global__ void k_wrz(const float* __restrict__ rW, const float* __restrict__ rb,
                      const float* __restrict__ uW, const float* __restrict__ ub,
                      float* __restrict__ Wrz, float* __restrict__ brz) {
    const int idx = blockIdx.x * 256 + threadIdx.x;   // 65536
    const int k = idx >> 8, n = idx & 255;
    Wrz[idx] = (n < 128) ? rW[k * 128 + n] : uW[k * 128 + (n - 128)];
    if (idx < 256) brz[idx] = (idx < 128) ? rb[idx] : ub[idx - 128];
}

__global__ void k_mm128(const float* __restrict__ A, const float* __restrict__ B,
                        float* __restrict__ C) {
    const int r = blockIdx.x, c = threadIdx.x;
    float s = 0.f;
#pragma unroll 8
    for (int k = 0; k < 128; k++) s = fmaf(A[r * 128 + k], B[k * 128 + c], s);
    C[r * 128 + c] = s;
}

__global__ void k_beff(const float* __restrict__ b, const float* __restrict__ W,
                       const float* __restrict__ W2, float* __restrict__ beff) {
    const int c = threadIdx.x;
    float s = b[c];
#pragma unroll 8
    for (int k = 0; k < 128; k++) s = fmaf(b[k], W[k * 128 + c] + W2[k * 128 + c], s);
    beff[c] = s;
}

__global__ void k_prop_to_cat(const float* __restrict__ prop, float* __restrict__ acat) {
    const int idx = blockIdx.x * blockDim.x + threadIdx.x;   // over MROWS*128
    const int r = idx >> 7, c = idx & 127;
    acat[(long long)r * 256 + 128 + c] = prop[idx];
}

__global__ void k_combine(const float* __restrict__ p0, const float* __restrict__ p1,
                          float* __restrict__ acat1) {
    const int idx = blockIdx.x * 256 + threadIdx.x;          // over MROWS*128
    const int r = idx >> 7, c = idx & 127;
    acat1[(long long)r * 256 + c] = p0[idx] + p1[idx];
}

__global__ void k_att_score(const float* __restrict__ t1, const float* __restrict__ W2,
                            const float* __restrict__ b2, float* __restrict__ att) {
    const int warp = (blockIdx.x * blockDim.x + threadIdx.x) >> 5;
    const int lane = threadIdx.x & 31;
    if (warp >= Bb * Nn) return;
    const float* row = t1 + (long long)warp * Dd;
    float s = 0.f;
#pragma unroll
    for (int c = lane; c < Dd; c += 32) s = fmaf(row[c], W2[c], s);
#pragma unroll
    for (int o = 16; o; o >>= 1) s += __shfl_xor_sync(0xffffffffu, s, o);
    if (lane == 0) att[warp] = s + b2[0];
}

__global__ void k_softmax(const float* __restrict__ att, float* __restrict__ aw) {
    const int b = blockIdx.x;
    const int n = threadIdx.x;              // 512
    __shared__ float red[Nn];
    const float v = att[b * Nn + n];
    red[n] = v;
    __syncthreads();
    for (int s = 256; s; s >>= 1) { if (n < s) red[n] = fmaxf(red[n], red[n + s]); __syncthreads(); }
    const float m = red[0];
    __syncthreads();
    const float e = __expf(v - m);
    red[n] = e;
    __syncthreads();
    for (int s = 256; s; s >>= 1) { if (n < s) red[n] += red[n + s]; __syncthreads(); }
    aw[b * Nn + n] = e / red[0];
}

__global__ void k_residual_part(const float* __restrict__ prop0, const float* __restrict__ edge0,
                                float* __restrict__ part) {
    const int ch = blockIdx.x;   // 0..19, 128 rows each
    const int b  = blockIdx.y;
    const int d  = threadIdx.x;  // 128
    float s = 0.f;
    const int r0 = ch * 128;
#pragma unroll 4
    for (int r = r0; r < r0 + 128; r++) {
        if (r < Nn) s += prop0[((long long)b * Nn + r) * Dd + d];
        else        s += edge0[((long long)b * Ee + (r - Nn)) * Dd + d];
    }
    part[(b * 20 + ch) * Dd + d] = s;
}

__global__ void k_final(const float* __restrict__ aw, const float* __restrict__ outn,
                        const float* __restrict__ part,
                        float* __restrict__ d_res, float* __restrict__ d_mul) {
    const int b = blockIdx.x;
    const int d = threadIdx.x;   // 128
    __shared__ float saw[Nn];
    for (int n = threadIdx.x; n < Nn; n += 128) saw[n] = aw[b * Nn + n];
    __syncthreads();
    const float* ob = outn + (long long)b * Nn * Dd;
    float acc = 0.f;
#pragma unroll 8
    for (int n = 0; n < Nn; n++) acc = fmaf(saw[n], ob[n * Dd + d], acc);
    float resid = 0.f;
#pragma unroll
    for (int c = 0; c < 20; c++) resid += part[(b * 20 + c) * Dd + d];
    resid *= (1.f / 2560.f);
    d_mul[b * Dd + d] = acc;
    d_res[b * Dd + d] = fmaxf(tanhf(acc) + resid, 0.f);
}

// ---------------- host launch ------------------------------------------------
static float* sym(const void* s) { void* p = nullptr; cudaGetSymbolAddress(&p, s); return (float*)p; }

extern "C" void kernel_launch(void* const* d_in, const int* in_sizes, int n_in,
                              void* d_out, int out_size) {
    const float* prop_in = (const float*)d_in[0];
    const float* edge_in = (const float*)d_in[1];
    const float* Amat    = (const float*)d_in[2];
    const float* link_W  = (const float*)d_in[4];
    const float* link_b  = (const float*)d_in[5];
    const float* reset_W = (const float*)d_in[6];
    const float* reset_b = (const float*)d_in[7];
    const float* upd_W   = (const float*)d_in[8];
    const float* upd_b   = (const float*)d_in[9];
    const float* trans_W = (const float*)d_in[10];
    const float* trans_b = (const float*)d_in[11];
    const float* att_W1  = (const float*)d_in[12];
    const float* att_b1  = (const float*)d_in[13];
    const float* att_W2  = (const float*)d_in[14];
    const float* att_b2  = (const float*)d_in[15];
    const float* out_W   = (const float*)d_in[16];
    const float* out_b   = (const float*)d_in[17];

    float* out      = (float*)d_out;
    float* out_res  = out;
    float* out_mul  = out + Bb * Dd;
    float* out_edge = out + 2 * Bb * Dd;

    float* acat1 = sym(g_acat1); float* acat2 = sym(g_acat2);
    float* zbuf  = sym(g_zbuf);  float* t1 = sym(g_t1); float* outn = sym(g_outn);
    float* split = sym(g_split); float* rA = sym(g_rA);
    float* Wrz = sym(g_Wrz); float* brz = sym(g_brz);
    float* W2 = sym(g_W2); float* W3 = sym(g_W3); float* beff = sym(g_beff);
    float* att = sym(g_att); float* aw = sym(g_aw); float* part = sym(g_part);

    // --- prep (independent of step loop) ---
    k_wrz<<<256, 256>>>(reset_W, reset_b, upd_W, upd_b, Wrz, brz);
    k_mm128<<<128, 128>>>(link_W, link_W, W2);
    k_mm128<<<128, 128>>>(W2, link_W, W3);
    k_beff<<<1, 128>>>(link_b, link_W, W2, beff);
    k_rowsumA<<<MROWS / 8, 256>>>(Amat, rA);
    k_prop_to_cat<<<(MROWS * 128) / 256, 256>>>(prop_in, acat1);

    // edge_states output: e3 = e0 @ W3 + beff  (direct to out)
    gemm_tf32<1><<<dim3(1, (Bb * Ee) / 128, 1), 256>>>(
        edge_in, 128, 0, W3, 128, 0, beff,
        out_edge, 128, 0, 0, nullptr, nullptr, nullptr, 128);

    // F_0 = A @ edge_init  (batched, split-K x2) -> split partials -> acat1[:,0:128]
    gemm_tf32<0><<<dim3(2, Nn / 128, Bb), 256>>>(
        Amat, Ee, (long long)Nn * Ee,
        edge_in, 128, (long long)Ee * 128, nullptr,
        split, 128, (long long)Nn * 128, (long long)MROWS * 128,
        nullptr, nullptr, nullptr, Ee / 2);
    k_combine<<<(MROWS * 128) / 256, 256>>>(split, split + (long long)MROWS * 128, acat1);

    // --- 3 GRU steps ---
    for (int s = 0; s < NSTEP; s++) {
        // a_cur = F_prev @ link_W + rA*link_b  (in place acat1[:,0:128], copy acat2)
        gemm_tf32<2><<<dim3(1, MROWS / 128, 1), 256>>>(
            acat1, 256, 0, link_W, 128, 0, link_b,
            acat1, 256, 0, 0, acat2, rA, nullptr, 128);
        // r|z = sigmoid(acat1 @ Wrz + brz): r*prop -> acat2[:,128:], z -> zbuf
        gemm_tf32<3><<<dim3(2, MROWS / 128, 1), 256>>>(
            acat1, 256, 0, Wrz, 256, 0, brz,
            zbuf, 128, 0, 0, acat2, nullptr, acat1, 256);
        // h = tanh(acat2 @ trans_W + trans_b); prop = (1-z)p + z*h -> acat1[:,128:]
        gemm_tf32<4><<<dim3(1, MROWS / 128, 1), 256>>>(
            acat2, 256, 0, trans_W, 128, 0, trans_b,
            acat1 + 128, 256, 0, 0, nullptr, zbuf, acat1 + 128, 256);
    }

    // --- attention pooling epilogue ---
    gemm_tf32<5><<<dim3(1, MROWS / 128, 1), 256>>>(
        acat1 + 128, 256, 0, att_W1, 128, 0, att_b1,
        t1, 128, 0, 0, nullptr, nullptr, nullptr, 128);
    k_att_score<<<(Bb * Nn) / 8, 256>>>(t1, att_W2, att_b2, att);
    k_softmax<<<Bb, Nn>>>(att, aw);
    gemm_tf32<5><<<dim3(1, MROWS / 128, 1), 256>>>(
        acat1 + 128, 256, 0, out_W, 128, 0, out_b,
        outn, 128, 0, 0, nullptr, nullptr, nullptr, 128);
    k_residual_part<<<dim3(20, Bb), Dd>>>(prop_in, edge_in, part);
    k_final<<<Bb, Dd>>>(aw, outn, part, out_res, out_mul);
}

// round 3
// speedup vs baseline: 3.5042x; 1.1171x over previous
#include <cuda_runtime.h>
#include <math.h>
#include <stdint.h>

#define Bb 32
#define Nn 512
#define Ee 2048
#define Dd 128
#define NSTEP 3
#define MROWS (Bb*Nn)          // 16384

// ---------------- scratch (device globals: allocation-free) ----------------
__device__ float g_F    [MROWS*Dd];     // F / a_cur (in-place per step)
__device__ float g_prop [MROWS*Dd];
__device__ float g_rp   [MROWS*Dd];     // r * prop
__device__ float g_zbuf [MROWS*Dd];
__device__ float g_t1   [MROWS*Dd];
__device__ float g_outn [MROWS*Dd];
__device__ float g_split[2*MROWS*Dd];   // F0 split-K partials
__device__ float g_rAp  [2*MROWS];      // rowsum(A) split partials
__device__ float g_rA   [MROWS];
__device__ float g_Wrz  [256*256];
__device__ float g_brz  [256];
__device__ float g_W2   [Dd*Dd];
__device__ float g_W3   [Dd*Dd];
__device__ float g_beff [Dd];
__device__ float g_att  [Bb*Nn];
__device__ float g_aw   [Bb*Nn];
__device__ float g_part [Bb*20*Dd];

// ---------------- tf32 helpers ---------------------------------------------
__device__ __forceinline__ uint32_t f2tf32(float x) {
    uint32_t u;
    asm("cvt.rna.tf32.f32 %0, %1;" : "=r"(u) : "f"(x));
    return u;
}
__device__ __forceinline__ void mma_tf32(float* c, const uint32_t* a, const uint32_t* b) {
    asm volatile("mma.sync.aligned.m16n8k8.row.col.f32.tf32.tf32.f32 "
                 "{%0,%1,%2,%3},{%4,%5,%6,%7},{%8,%9},{%0,%1,%2,%3};"
                 : "+f"(c[0]), "+f"(c[1]), "+f"(c[2]), "+f"(c[3])
                 : "r"(a[0]), "r"(a[1]), "r"(a[2]), "r"(a[3]),
                   "r"(b[0]), "r"(b[1]));
}

// ---------------- tf32 GEMM, BM=128 BN=128 BK=32, 512 thr, reg-prefetch ----
// EPI: 0=splitK plain + rowsum(A) partials   1=+bias
//      2=ACUR  v+rA[r]*bias (in-place)       3=RZ sigmoid -> rp / zbuf
//      4=HHAT tanh + GRU blend -> prop       5=tanh(+bias)
// SPLITA: A operand is [A | A2], two K=128 row-major segments (lda=128 each).
template<int EPI, bool SPLITA>
__global__ __launch_bounds__(512)
void gemm_tf32(const float* __restrict__ A, const float* __restrict__ A2,
               int lda, long long sA,
               const float* __restrict__ W, int ldb, long long sB,
               const float* __restrict__ bias,
               float* __restrict__ C, long long sC, long long sCx,
               float* __restrict__ C2,
               const float* __restrict__ aux1,   // rA (EPI2) / zbuf (EPI4)
               const float* __restrict__ aux2,   // prop (EPI3/4)
               float* __restrict__ rAp,
               int Klen)
{
    __shared__ uint32_t As[128][36];   // [m][k]  (stride 144B, STS.128 ok)
    __shared__ uint32_t Bs[32][132];   // [k][n]

    const int tid  = threadIdx.x;
    const int warp = tid >> 5, lane = tid & 31;
    const int wm = warp & 3, wn = warp >> 2;      // 4x4 warp grid, 32x32 tiles
    const int group = lane >> 2, tig = lane & 3;

    const int  n0g  = (EPI == 0) ? 0 : blockIdx.x * 128;
    const int  kOff = (EPI == 0) ? blockIdx.x * Klen : 0;
    const int  m0   = blockIdx.y * 128;
    const long long bz = blockIdx.z;
    A += bz * sA;
    W += bz * sB;
    C += bz * sC + ((EPI == 0) ? blockIdx.x * sCx : 0ll);

    // loaders: A row = tid>>2 (0..127), k base = (tid&3)*8 ; B k = tid>>4, n = (tid&15)*8
    const int ar  = tid >> 2, ac  = (tid & 3) * 8;
    const int bkr = tid >> 4, bcb = (tid & 15) * 8;

    float acc[2][4][4];
#pragma unroll
    for (int i = 0; i < 2; i++)
#pragma unroll
        for (int j = 0; j < 4; j++)
#pragma unroll
            for (int q = 0; q < 4; q++) acc[i][j][q] = 0.f;

    float rsum = 0.f;
    float4 a0, a1, b0, b1;

    auto loadTile = [&](int k0) {
        const float* asrc;
        if (SPLITA && k0 >= 128)
            asrc = A2 + (size_t)(m0 + ar) * 128 + (k0 - 128) + ac;
        else
            asrc = A + (size_t)(m0 + ar) * lda + kOff + k0 + ac;
        a0 = *(const float4*)asrc;
        a1 = *(const float4*)(asrc + 4);
        if (EPI == 0)
            rsum += ((a0.x + a0.y) + (a0.z + a0.w)) + ((a1.x + a1.y) + (a1.z + a1.w));
        const float* bsrc = W + (size_t)(kOff + k0 + bkr) * ldb + n0g + bcb;
        b0 = *(const float4*)bsrc;
        b1 = *(const float4*)(bsrc + 4);
    };

    loadTile(0);

    for (int k0 = 0; k0 < Klen; k0 += 32) {
        // stage to smem (convert to tf32)
        uint32_t* ad = &As[ar][ac];
        ad[0] = f2tf32(a0.x); ad[1] = f2tf32(a0.y); ad[2] = f2tf32(a0.z); ad[3] = f2tf32(a0.w);
        ad[4] = f2tf32(a1.x); ad[5] = f2tf32(a1.y); ad[6] = f2tf32(a1.z); ad[7] = f2tf32(a1.w);
        uint32_t* bd = &Bs[bkr][bcb];
        bd[0] = f2tf32(b0.x); bd[1] = f2tf32(b0.y); bd[2] = f2tf32(b0.z); bd[3] = f2tf32(b0.w);
        bd[4] = f2tf32(b1.x); bd[5] = f2tf32(b1.y); bd[6] = f2tf32(b1.z); bd[7] = f2tf32(b1.w);
        __syncthreads();

        if (k0 + 32 < Klen) loadTile(k0 + 32);   // prefetch next tile into regs

#pragma unroll
        for (int k8 = 0; k8 < 4; k8++) {
            const int kb = k8 * 8;
            uint32_t af[2][4], bf[4][2];
#pragma unroll
            for (int mi = 0; mi < 2; mi++) {
                const int m = wm * 32 + mi * 16;
                af[mi][0] = As[m + group][kb + tig];
                af[mi][1] = As[m + group + 8][kb + tig];
                af[mi][2] = As[m + group][kb + tig + 4];
                af[mi][3] = As[m + group + 8][kb + tig + 4];
            }
#pragma unroll
            for (int ni = 0; ni < 4; ni++) {
                const int n = wn * 32 + ni * 8;
                bf[ni][0] = Bs[kb + tig][n + group];
                bf[ni][1] = Bs[kb + tig + 4][n + group];
            }
#pragma unroll
            for (int mi = 0; mi < 2; mi++)
#pragma unroll
                for (int ni = 0; ni < 4; ni++)
                    mma_tf32(acc[mi][ni], af[mi], bf[ni]);
        }
        __syncthreads();
    }

    // rowsum(A) partials (EPI0 only): 4 loader threads per row -> quad reduce
    if (EPI == 0) {
        float s = rsum;
        s += __shfl_xor_sync(0xffffffffu, s, 1);
        s += __shfl_xor_sync(0xffffffffu, s, 2);
        if ((tid & 3) == 0)
            rAp[(long long)blockIdx.x * MROWS + bz * Nn + m0 + ar] = s;
    }

    // ---- epilogue ----
#pragma unroll
    for (int mi = 0; mi < 2; mi++) {
#pragma unroll
        for (int ni = 0; ni < 4; ni++) {
            const int cl = wn * 32 + ni * 8 + 2 * tig;
#pragma unroll
            for (int rr = 0; rr < 2; rr++) {
                const long long r = m0 + wm * 32 + mi * 16 + group + rr * 8;
#pragma unroll
                for (int cc = 0; cc < 2; cc++) {
                    float v = acc[mi][ni][rr * 2 + cc];
                    const int col  = cl + cc;
                    const int gcol = n0g + col;
                    if (EPI == 0) {
                        C[r * 128 + col] = v;
                    } else if (EPI == 1) {
                        C[r * 128 + col] = v + bias[col];
                    } else if (EPI == 2) {
                        C[r * 128 + col] = v + aux1[r] * bias[col];
                    } else if (EPI == 3) {
                        v = 1.f / (1.f + __expf(-(v + bias[gcol])));
                        if (blockIdx.x == 0) C2[r * 128 + col] = v * aux2[r * 128 + col];
                        else                 C [r * 128 + col] = v;
                    } else if (EPI == 4) {
                        const float h = tanhf(v + bias[col]);
                        const float z = aux1[r * 128 + col];
                        const float p = aux2[r * 128 + col];
                        C[r * 128 + col] = fmaf(z, h - p, p);
                    } else { // 5
                        C[r * 128 + col] = tanhf(v + bias[col]);
                    }
                }
            }
        }
    }
}

// ---------------- helper kernels --------------------------------------------
__global__ void k_wrz(const float* __restrict__ rW, const float* __restrict__ rb,
                      const float* __restrict__ uW, const float* __restrict__ ub,
                      float* __restrict__ Wrz, float* __restrict__ brz) {
    const int idx = blockIdx.x * 256 + threadIdx.x;   // 65536
    const int k = idx >> 8, n = idx & 255;
    Wrz[idx] = (n < 128) ? rW[k * 128 + n] : uW[k * 128 + (n - 128)];
    if (idx < 256) brz[idx] = (idx < 128) ? rb[idx] : ub[idx - 128];
}

// C[r][c] = sum_k A[r][k] B[k][c], 128^3, fp32. Block = row, A row in smem, 4-way ILP.
__global__ void k_mm128(const float* __restrict__ A, const float* __restrict__ B,
                        float* __restrict__ C) {
    const int r = blockIdx.x, c = threadIdx.x;
    __shared__ float sA[128];
    sA[c] = A[r * 128 + c];
    __syncthreads();
    float s0 = 0.f, s1 = 0.f, s2 = 0.f, s3 = 0.f;
#pragma unroll
    for (int k = 0; k < 128; k += 4) {
        s0 = fmaf(sA[k + 0], B[(k + 0) * 128 + c], s0);
        s1 = fmaf(sA[k + 1], B[(k + 1) * 128 + c], s1);
        s2 = fmaf(sA[k + 2], B[(k + 2) * 128 + c], s2);
        s3 = fmaf(sA[k + 3], B[(k + 3) * 128 + c], s3);
    }
    C[r * 128 + c] = (s0 + s1) + (s2 + s3);
}

// beff[c] = b[c] + sum_k b[k] * (W[k][c] + W2[k][c])   — warp per column
__global__ void k_beff(const float* __restrict__ b, const float* __restrict__ W,
                       const float* __restrict__ W2, float* __restrict__ beff) {
    const int c    = blockIdx.x * 8 + (threadIdx.x >> 5);
    const int lane = threadIdx.x & 31;
    float s = 0.f;
#pragma unroll
    for (int k = lane; k < 128; k += 32)
        s = fmaf(b[k], W[k * 128 + c] + W2[k * 128 + c], s);
#pragma unroll
    for (int o = 16; o; o >>= 1) s += __shfl_xor_sync(0xffffffffu, s, o);
    if (lane == 0) beff[c] = b[c] + s;
}

__global__ void k_combine(const float* __restrict__ sp, float* __restrict__ F,
                          const float* __restrict__ rAp, float* __restrict__ rA) {
    const int idx = blockIdx.x * 256 + threadIdx.x;          // MROWS*128
    F[idx] = sp[idx] + sp[(long long)MROWS * 128 + idx];
    if (idx < MROWS) rA[idx] = rAp[idx] + rAp[MROWS + idx];
}

__global__ void k_att_score(const float* __restrict__ t1, const float* __restrict__ W2,
                            const float* __restrict__ b2, float* __restrict__ att) {
    const int warp = (blockIdx.x * blockDim.x + threadIdx.x) >> 5;
    const int lane = threadIdx.x & 31;
    if (warp >= Bb * Nn) return;
    const float* row = t1 + (long long)warp * Dd;
    float s = 0.f;
#pragma unroll
    for (int c = lane; c < Dd; c += 32) s = fmaf(row[c], W2[c], s);
#pragma unroll
    for (int o = 16; o; o >>= 1) s += __shfl_xor_sync(0xffffffffu, s, o);
    if (lane == 0) att[warp] = s + b2[0];
}

__global__ void k_softmax(const float* __restrict__ att, float* __restrict__ aw) {
    const int b = blockIdx.x;
    const int n = threadIdx.x;              // 512
    __shared__ float red[Nn];
    const float v = att[b * Nn + n];
    red[n] = v;
    __syncthreads();
    for (int s = 256; s; s >>= 1) { if (n < s) red[n] = fmaxf(red[n], red[n + s]); __syncthreads(); }
    const float m = red[0];
    __syncthreads();
    const float e = __expf(v - m);
    red[n] = e;
    __syncthreads();
    for (int s = 256; s; s >>= 1) { if (n < s) red[n] += red[n + s]; __syncthreads(); }
    aw[b * Nn + n] = e / red[0];
}

__global__ void k_residual_part(const float* __restrict__ prop0, const float* __restrict__ edge0,
                                float* __restrict__ part) {
    const int ch = blockIdx.x;   // 0..19, 128 rows each
    const int b  = blockIdx.y;
    const int d  = threadIdx.x;  // 128
    float s = 0.f;
    const int r0 = ch * 128;
#pragma unroll 4
    for (int r = r0; r < r0 + 128; r++) {
        if (r < Nn) s += prop0[((long long)b * Nn + r) * Dd + d];
        else        s += edge0[((long long)b * Ee + (r - Nn)) * Dd + d];
    }
    part[(b * 20 + ch) * Dd + d] = s;
}

__global__ void k_final(const float* __restrict__ aw, const float* __restrict__ outn,
                        const float* __restrict__ part,
                        float* __restrict__ d_res, float* __restrict__ d_mul) {
    const int b = blockIdx.x;
    const int d = threadIdx.x;   // 128
    __shared__ float saw[Nn];
    for (int n = threadIdx.x; n < Nn; n += 128) saw[n] = aw[b * Nn + n];
    __syncthreads();
    const float* ob = outn + (long long)b * Nn * Dd;
    float acc = 0.f;
#pragma unroll 8
    for (int n = 0; n < Nn; n++) acc = fmaf(saw[n], ob[n * Dd + d], acc);
    float resid = 0.f;
#pragma unroll
    for (int c = 0; c < 20; c++) resid += part[(b * 20 + c) * Dd + d];
    resid *= (1.f / 2560.f);
    d_mul[b * Dd + d] = acc;
    d_res[b * Dd + d] = fmaxf(tanhf(acc) + resid, 0.f);
}

// ---------------- host launch ------------------------------------------------
static float* sym(const void* s) { void* p = nullptr; cudaGetSymbolAddress(&p, s); return (float*)p; }

extern "C" void kernel_launch(void* const* d_in, const int* in_sizes, int n_in,
                              void* d_out, int out_size) {
    const float* prop_in = (const float*)d_in[0];
    const float* edge_in = (const float*)d_in[1];
    const float* Amat    = (const float*)d_in[2];
    const float* link_W  = (const float*)d_in[4];
    const float* link_b  = (const float*)d_in[5];
    const float* reset_W = (const float*)d_in[6];
    const float* reset_b = (const float*)d_in[7];
    const float* upd_W   = (const float*)d_in[8];
    const float* upd_b   = (const float*)d_in[9];
    const float* trans_W = (const float*)d_in[10];
    const float* trans_b = (const float*)d_in[11];
    const float* att_W1  = (const float*)d_in[12];
    const float* att_b1  = (const float*)d_in[13];
    const float* att_W2  = (const float*)d_in[14];
    const float* att_b2  = (const float*)d_in[15];
    const float* out_W   = (const float*)d_in[16];
    const float* out_b   = (const float*)d_in[17];

    float* out      = (float*)d_out;
    float* out_res  = out;
    float* out_mul  = out + Bb * Dd;
    float* out_edge = out + 2 * Bb * Dd;

    float* F = sym(g_F); float* prop = sym(g_prop); float* rp = sym(g_rp);
    float* zbuf = sym(g_zbuf); float* t1 = sym(g_t1); float* outn = sym(g_outn);
    float* split = sym(g_split); float* rAp = sym(g_rAp); float* rA = sym(g_rA);
    float* Wrz = sym(g_Wrz); float* brz = sym(g_brz);
    float* W2 = sym(g_W2); float* W3 = sym(g_W3); float* beff = sym(g_beff);
    float* att = sym(g_att); float* aw = sym(g_aw); float* part = sym(g_part);

    // --- prep ---
    k_wrz<<<256, 256>>>(reset_W, reset_b, upd_W, upd_b, Wrz, brz);
    k_mm128<<<128, 128>>>(link_W, link_W, W2);
    k_mm128<<<128, 128>>>(W2, link_W, W3);
    k_beff<<<16, 256>>>(link_b, link_W, W2, beff);

    // edge_states output: e3 = e0 @ W3 + beff
    gemm_tf32<1, false><<<dim3(1, (Bb * Ee) / 128, 1), 512>>>(
        edge_in, nullptr, 128, 0, W3, 128, 0, beff,
        out_edge, 0, 0, nullptr, nullptr, nullptr, nullptr, 128);

    // F0 = A @ edge_init (batched, split-K x2) + rowsum(A) partials
    gemm_tf32<0, false><<<dim3(2, Nn / 128, Bb), 512>>>(
        Amat, nullptr, Ee, (long long)Nn * Ee,
        edge_in, 128, (long long)Ee * 128, nullptr,
        split, (long long)Nn * 128, (long long)MROWS * 128,
        nullptr, nullptr, nullptr, rAp, Ee / 2);
    k_combine<<<(MROWS * 128) / 256, 256>>>(split, F, rAp, rA);

    // --- 3 GRU steps ---
    const float* prop_cur = prop_in;
    for (int s = 0; s < NSTEP; s++) {
        // a_cur = F @ link_W + rA*link_b   (in-place in F)
        gemm_tf32<2, false><<<dim3(1, MROWS / 128, 1), 512>>>(
            F, nullptr, 128, 0, link_W, 128, 0, link_b,
            F, 0, 0, nullptr, rA, nullptr, nullptr, 128);
        // [r|z] = sigmoid([a_cur|prop] @ Wrz + brz) : rp = r*prop, zbuf = z
        gemm_tf32<3, true><<<dim3(2, MROWS / 128, 1), 512>>>(
            F, prop_cur, 128, 0, Wrz, 256, 0, brz,
            zbuf, 0, 0, rp, nullptr, prop_cur, nullptr, 256);
        // h = tanh([a_cur|rp] @ trans_W + b); prop = p + z*(h-p)
        gemm_tf32<4, true><<<dim3(1, MROWS / 128, 1), 512>>>(
            F, rp, 128, 0, trans_W, 128, 0, trans_b,
            prop, 0, 0, nullptr, zbuf, prop_cur, nullptr, 256);
        prop_cur = prop;
    }

    // --- attention pooling epilogue ---
    gemm_tf32<5, false><<<dim3(1, MROWS / 128, 1), 512>>>(
        prop, nullptr, 128, 0, att_W1, 128, 0, att_b1,
        t1, 0, 0, nullptr, nullptr, nullptr, nullptr, 128);
    k_att_score<<<(Bb * Nn) / 8, 256>>>(t1, att_W2, att_b2, att);
    k_softmax<<<Bb, Nn>>>(att, aw);
    gemm_tf32<5, false><<<dim3(1, MROWS / 128, 1), 512>>>(
        prop, nullptr, 128, 0, out_W, 128, 0, out_b,
        outn, 0, 0, nullptr, nullptr, nullptr, nullptr, 128);
    k_residual_part<<<dim3(20, Bb), Dd>>>(prop_in, edge_in, part);
    k_final<<<Bb, Dd>>>(aw, outn, part, out_res, out_mul);
}

// round 5
// speedup vs baseline: 4.1122x; 1.1735x over previous
#include <cuda_runtime.h>
#include <cuda_fp16.h>
#include <math.h>
#include <stdint.h>

#define Bb 32
#define Nn 512
#define Ee 2048
#define Dd 128
#define NSTEP 3
#define MROWS (Bb*Nn)          // 16384

// ---------------- scratch (device globals: allocation-free) ----------------
__device__ float g_F    [MROWS*Dd];
__device__ float g_prop [MROWS*Dd];
__device__ float g_rp   [MROWS*Dd];
__device__ float g_zbuf [MROWS*Dd];
__device__ float g_t1   [MROWS*Dd];
__device__ float g_outn [MROWS*Dd];
__device__ float g_split[2*MROWS*Dd];
__device__ float g_rAp  [2*MROWS];
__device__ float g_rA   [MROWS];
__device__ float g_WrzT [256*256];    // [N=256][K=256]
__device__ float g_brz  [256];
__device__ float g_linkWT[Dd*Dd];
__device__ float g_transWT[Dd*256];   // [N=128][K=256]
__device__ float g_attW1T[Dd*Dd];
__device__ float g_outWT [Dd*Dd];
__device__ float g_W2   [Dd*Dd];
__device__ float g_W3   [Dd*Dd];
__device__ float g_W3T  [Dd*Dd];
__device__ float g_beff [Dd];
__device__ float g_att  [Bb*Nn];
__device__ float g_aw   [Bb*Nn];
__device__ float g_part [Bb*20*Dd];

// ---------------- fp16 mma helpers ------------------------------------------
__device__ __forceinline__ uint32_t packh2(float x, float y) {
    __half2 h = __floats2half2_rn(x, y);
    return *(uint32_t*)&h;
}
__device__ __forceinline__ void mma_f16(float* c, const uint32_t* a, const uint32_t* b) {
    asm volatile("mma.sync.aligned.m16n8k16.row.col.f32.f16.f16.f32 "
                 "{%0,%1,%2,%3},{%4,%5,%6,%7},{%8,%9},{%0,%1,%2,%3};"
                 : "+f"(c[0]), "+f"(c[1]), "+f"(c[2]), "+f"(c[3])
                 : "r"(a[0]), "r"(a[1]), "r"(a[2]), "r"(a[3]),
                   "r"(b[0]), "r"(b[1]));
}

#define LDW 20   // smem row stride in words (16 data half2-pairs + 4 pad)

// ---------------- fp16 HMMA GEMM, 128x128 tile, BK=32, double-buffered -----
// A [M,K] row-major fp32; B = WT [N,K] row-major fp32 (or TRANSB: [K,N]).
// EPI: 0=splitK plain + rowsum(A)   1=+bias   2=v+rA[r]*bias (in-place acur)
//      3=rz sigmoid (bx0: rp=r*prop -> C2 ; bx1: z -> C)
//      4=hhat tanh + GRU blend -> C   5=tanh(+bias)
template<int EPI, bool SPLITA, bool TRANSB>
__global__ __launch_bounds__(512)
void gemm_h(const float* __restrict__ A, const float* __restrict__ A2, int lda, long long sA,
            const float* __restrict__ Bm, int ldb, long long sB,
            const float* __restrict__ bias,
            float* __restrict__ C, long long sC, long long sCx,
            float* __restrict__ C2,
            const float* __restrict__ aux1, const float* __restrict__ aux2,
            float* __restrict__ rAp, int Klen)
{
    __shared__ uint32_t As[2][128 * LDW];
    __shared__ uint32_t Bs[2][128 * LDW];

    const int tid  = threadIdx.x;
    const int warp = tid >> 5, lane = tid & 31;
    const int wm = warp & 3, wn = warp >> 2;      // 4x4 warp grid, 32x32 tiles
    const int group = lane >> 2, tig = lane & 3;

    const int  n0g  = (EPI == 3) ? blockIdx.x * 128 : 0;
    const int  kOff = (EPI == 0) ? blockIdx.x * Klen : 0;
    const int  m0   = blockIdx.y * 128;
    const long long bz = blockIdx.z;
    A  += bz * sA;
    Bm += bz * sB;
    C  += bz * sC + ((EPI == 0) ? blockIdx.x * sCx : 0ll);

    // A loader: row ar (4 thr/row), 8 floats at k-offset (tid&3)*8
    const int ar = tid >> 2, ak2 = (tid & 3) * 4;
    // TRANSB B loader: pair-row k2 = tid&15, n base = (tid>>4)*4
    const int tk2 = tid & 15, tnb = (tid >> 4) * 4;

    float acc[2][4][4];
#pragma unroll
    for (int i = 0; i < 2; i++)
#pragma unroll
        for (int j = 0; j < 4; j++)
#pragma unroll
            for (int q = 0; q < 4; q++) acc[i][j][q] = 0.f;

    float rsum = 0.f;
    float4 a0, a1, b0, b1;

    auto loadRegs = [&](int it) {
        const int k0 = kOff + it * 32;
        const float* asrc = (SPLITA && it * 32 >= 128)
            ? (A2 + (size_t)(m0 + ar) * 128 + (it * 32 - 128) + ak2 * 2)
            : (A  + (size_t)(m0 + ar) * lda + k0 + ak2 * 2);
        a0 = *(const float4*)asrc;
        a1 = *(const float4*)(asrc + 4);
        if (EPI == 0)
            rsum += ((a0.x + a0.y) + (a0.z + a0.w)) + ((a1.x + a1.y) + (a1.z + a1.w));
        if (!TRANSB) {
            const float* bsrc = Bm + (size_t)(n0g + ar) * ldb + k0 + ak2 * 2;
            b0 = *(const float4*)bsrc;
            b1 = *(const float4*)(bsrc + 4);
        } else {
            const float* bsrc = Bm + (size_t)(k0 + 2 * tk2) * ldb + tnb;
            b0 = *(const float4*)bsrc;           // k even row
            b1 = *(const float4*)(bsrc + ldb);   // k odd row
        }
    };

    auto stage = [&](int buf) {
        uint4 aw = { packh2(a0.x, a0.y), packh2(a0.z, a0.w),
                     packh2(a1.x, a1.y), packh2(a1.z, a1.w) };
        *(uint4*)&As[buf][ar * LDW + ak2] = aw;
        if (!TRANSB) {
            uint4 bw = { packh2(b0.x, b0.y), packh2(b0.z, b0.w),
                         packh2(b1.x, b1.y), packh2(b1.z, b1.w) };
            *(uint4*)&Bs[buf][ar * LDW + ak2] = bw;
        } else {
            Bs[buf][(tnb + 0) * LDW + tk2] = packh2(b0.x, b1.x);
            Bs[buf][(tnb + 1) * LDW + tk2] = packh2(b0.y, b1.y);
            Bs[buf][(tnb + 2) * LDW + tk2] = packh2(b0.z, b1.z);
            Bs[buf][(tnb + 3) * LDW + tk2] = packh2(b0.w, b1.w);
        }
    };

    const int niter = Klen / 32;
    loadRegs(0);
    stage(0);
    __syncthreads();

    for (int it = 0; it < niter; it++) {
        const int buf = it & 1;
        if (it + 1 < niter) loadRegs(it + 1);

#pragma unroll
        for (int s = 0; s < 2; s++) {
            const int kb = s * 8;
            uint32_t af[2][4], bf[4][2];
#pragma unroll
            for (int mi = 0; mi < 2; mi++) {
                const int m = wm * 32 + mi * 16;
                af[mi][0] = As[buf][(m + group) * LDW + kb + tig];
                af[mi][1] = As[buf][(m + group + 8) * LDW + kb + tig];
                af[mi][2] = As[buf][(m + group) * LDW + kb + tig + 4];
                af[mi][3] = As[buf][(m + group + 8) * LDW + kb + tig + 4];
            }
#pragma unroll
            for (int ni = 0; ni < 4; ni++) {
                const int n = wn * 32 + ni * 8;
                bf[ni][0] = Bs[buf][(n + group) * LDW + kb + tig];
                bf[ni][1] = Bs[buf][(n + group) * LDW + kb + tig + 4];
            }
#pragma unroll
            for (int mi = 0; mi < 2; mi++)
#pragma unroll
                for (int ni = 0; ni < 4; ni++)
                    mma_f16(acc[mi][ni], af[mi], bf[ni]);
        }

        if (it + 1 < niter) stage((it + 1) & 1);
        __syncthreads();
    }

    // rowsum(A) partials (EPI0): quad reduce across (tid&3)
    if (EPI == 0) {
        float s = rsum;
        s += __shfl_xor_sync(0xffffffffu, s, 1);
        s += __shfl_xor_sync(0xffffffffu, s, 2);
        if ((tid & 3) == 0)
            rAp[(long long)blockIdx.x * MROWS + bz * Nn + m0 + ar] = s;
    }

    // ---- epilogue ----
#pragma unroll
    for (int mi = 0; mi < 2; mi++) {
#pragma unroll
        for (int ni = 0; ni < 4; ni++) {
            const int cl = wn * 32 + ni * 8 + 2 * tig;
#pragma unroll
            for (int rr = 0; rr < 2; rr++) {
                const long long r = m0 + wm * 32 + mi * 16 + group + rr * 8;
#pragma unroll
                for (int cc = 0; cc < 2; cc++) {
                    float v = acc[mi][ni][rr * 2 + cc];
                    const int col  = cl + cc;
                    const int gcol = n0g + col;
                    if (EPI == 0) {
                        C[r * 128 + col] = v;
                    } else if (EPI == 1) {
                        C[r * 128 + col] = v + bias[col];
                    } else if (EPI == 2) {
                        C[r * 128 + col] = v + aux1[r] * bias[col];
                    } else if (EPI == 3) {
                        v = 1.f / (1.f + __expf(-(v + bias[gcol])));
                        if (blockIdx.x == 0) C2[r * 128 + col] = v * aux2[r * 128 + col];
                        else                 C [r * 128 + col] = v;
                    } else if (EPI == 4) {
                        const float h = tanhf(v + bias[col]);
                        const float z = aux1[r * 128 + col];
                        const float p = aux2[r * 128 + col];
                        C[r * 128 + col] = fmaf(z, h - p, p);
                    } else { // 5
                        C[r * 128 + col] = tanhf(v + bias[col]);
                    }
                }
            }
        }
    }
}

// ---------------- prep / helper kernels --------------------------------------
__global__ void k_wrzT(const float* __restrict__ rW, const float* __restrict__ rb,
                       const float* __restrict__ uW, const float* __restrict__ ub,
                       float* __restrict__ WrzT, float* __restrict__ brz) {
    const int n = blockIdx.x, k = threadIdx.x;   // 256 x 256
    WrzT[n * 256 + k] = (n < 128) ? rW[k * 128 + n] : uW[k * 128 + (n - 128)];
    if (n == 0) brz[k] = (k < 128) ? rb[k] : ub[k - 128];
}
__global__ void k_t128(const float* __restrict__ W, float* __restrict__ WT) {
    const int n = blockIdx.x, k = threadIdx.x;   // 128 x 128
    WT[n * 128 + k] = W[k * 128 + n];
}
__global__ void k_transWT(const float* __restrict__ W, float* __restrict__ WT) {
    const int n = blockIdx.x, k = threadIdx.x;   // 128 blocks x 256 thr
    WT[n * 256 + k] = W[k * 128 + n];
}
__global__ void k_mm128(const float* __restrict__ A, const float* __restrict__ B,
                        float* __restrict__ C) {
    const int r = blockIdx.x, c = threadIdx.x;
    __shared__ float sA[128];
    sA[c] = A[r * 128 + c];
    __syncthreads();
    float s0 = 0.f, s1 = 0.f, s2 = 0.f, s3 = 0.f;
#pragma unroll
    for (int k = 0; k < 128; k += 4) {
        s0 = fmaf(sA[k + 0], B[(k + 0) * 128 + c], s0);
        s1 = fmaf(sA[k + 1], B[(k + 1) * 128 + c], s1);
        s2 = fmaf(sA[k + 2], B[(k + 2) * 128 + c], s2);
        s3 = fmaf(sA[k + 3], B[(k + 3) * 128 + c], s3);
    }
    C[r * 128 + c] = (s0 + s1) + (s2 + s3);
}
__global__ void k_beff(const float* __restrict__ b, const float* __restrict__ W,
                       const float* __restrict__ W2, float* __restrict__ beff) {
    const int c    = blockIdx.x * 8 + (threadIdx.x >> 5);
    const int lane = threadIdx.x & 31;
    float s = 0.f;
#pragma unroll
    for (int k = lane; k < 128; k += 32)
        s = fmaf(b[k], W[k * 128 + c] + W2[k * 128 + c], s);
#pragma unroll
    for (int o = 16; o; o >>= 1) s += __shfl_xor_sync(0xffffffffu, s, o);
    if (lane == 0) beff[c] = b[c] + s;
}
__global__ void k_combine(const float* __restrict__ sp, float* __restrict__ F,
                          const float* __restrict__ rAp, float* __restrict__ rA) {
    const int idx = blockIdx.x * 256 + threadIdx.x;
    F[idx] = sp[idx] + sp[(long long)MROWS * 128 + idx];
    if (idx < MROWS) rA[idx] = rAp[idx] + rAp[MROWS + idx];
}
__global__ void k_att_score(const float* __restrict__ t1, const float* __restrict__ W2,
                            const float* __restrict__ b2, float* __restrict__ att) {
    const int warp = (blockIdx.x * blockDim.x + threadIdx.x) >> 5;
    const int lane = threadIdx.x & 31;
    if (warp >= Bb * Nn) return;
    const float* row = t1 + (long long)warp * Dd;
    float s = 0.f;
#pragma unroll
    for (int c = lane; c < Dd; c += 32) s = fmaf(row[c], W2[c], s);
#pragma unroll
    for (int o = 16; o; o >>= 1) s += __shfl_xor_sync(0xffffffffu, s, o);
    if (lane == 0) att[warp] = s + b2[0];
}
__global__ void k_softmax(const float* __restrict__ att, float* __restrict__ aw) {
    const int b = blockIdx.x;
    const int n = threadIdx.x;              // 512
    __shared__ float red[Nn];
    const float v = att[b * Nn + n];
    red[n] = v;
    __syncthreads();
    for (int s = 256; s; s >>= 1) { if (n < s) red[n] = fmaxf(red[n], red[n + s]); __syncthreads(); }
    const float m = red[0];
    __syncthreads();
    const float e = __expf(v - m);
    red[n] = e;
    __syncthreads();
    for (int s = 256; s; s >>= 1) { if (n < s) red[n] += red[n + s]; __syncthreads(); }
    aw[b * Nn + n] = e / red[0];
}
__global__ void k_residual_part(const float* __restrict__ prop0, const float* __restrict__ edge0,
                                float* __restrict__ part) {
    const int ch = blockIdx.x, b = blockIdx.y, d = threadIdx.x;
    float s = 0.f;
    const int r0 = ch * 128;
#pragma unroll 4
    for (int r = r0; r < r0 + 128; r++) {
        if (r < Nn) s += prop0[((long long)b * Nn + r) * Dd + d];
        else        s += edge0[((long long)b * Ee + (r - Nn)) * Dd + d];
    }
    part[(b * 20 + ch) * Dd + d] = s;
}
__global__ void k_final(const float* __restrict__ aw, const float* __restrict__ outn,
                        const float* __restrict__ part,
                        float* __restrict__ d_res, float* __restrict__ d_mul) {
    const int b = blockIdx.x, d = threadIdx.x;
    __shared__ float saw[Nn];
    for (int n = threadIdx.x; n < Nn; n += 128) saw[n] = aw[b * Nn + n];
    __syncthreads();
    const float* ob = outn + (long long)b * Nn * Dd;
    float acc = 0.f;
#pragma unroll 8
    for (int n = 0; n < Nn; n++) acc = fmaf(saw[n], ob[n * Dd + d], acc);
    float resid = 0.f;
#pragma unroll
    for (int c = 0; c < 20; c++) resid += part[(b * 20 + c) * Dd + d];
    resid *= (1.f / 2560.f);
    d_mul[b * Dd + d] = acc;
    d_res[b * Dd + d] = fmaxf(tanhf(acc) + resid, 0.f);
}

// ---------------- host launch --------------------------------------------------
static float* sym(const void* s) { void* p = nullptr; cudaGetSymbolAddress(&p, s); return (float*)p; }

extern "C" void kernel_launch(void* const* d_in, const int* in_sizes, int n_in,
                              void* d_out, int out_size) {
    const float* prop_in = (const float*)d_in[0];
    const float* edge_in = (const float*)d_in[1];
    const float* Amat    = (const float*)d_in[2];
    const float* link_W  = (const float*)d_in[4];
    const float* link_b  = (const float*)d_in[5];
    const float* reset_W = (const float*)d_in[6];
    const float* reset_b = (const float*)d_in[7];
    const float* upd_W   = (const float*)d_in[8];
    const float* upd_b   = (const float*)d_in[9];
    const float* trans_W = (const float*)d_in[10];
    const float* trans_b = (const float*)d_in[11];
    const float* att_W1  = (const float*)d_in[12];
    const float* att_b1  = (const float*)d_in[13];
    const float* att_W2  = (const float*)d_in[14];
    const float* att_b2  = (const float*)d_in[15];
    const float* out_W   = (const float*)d_in[16];
    const float* out_b   = (const float*)d_in[17];

    float* out      = (float*)d_out;
    float* out_res  = out;
    float* out_mul  = out + Bb * Dd;
    float* out_edge = out + 2 * Bb * Dd;

    float* F = sym(g_F); float* prop = sym(g_prop); float* rp = sym(g_rp);
    float* zbuf = sym(g_zbuf); float* t1 = sym(g_t1); float* outn = sym(g_outn);
    float* split = sym(g_split); float* rAp = sym(g_rAp); float* rA = sym(g_rA);
    float* WrzT = sym(g_WrzT); float* brz = sym(g_brz);
    float* linkWT = sym(g_linkWT); float* transWT = sym(g_transWT);
    float* attW1T = sym(g_attW1T); float* outWT = sym(g_outWT);
    float* W2 = sym(g_W2); float* W3 = sym(g_W3); float* W3T = sym(g_W3T);
    float* beff = sym(g_beff);
    float* att = sym(g_att); float* aw = sym(g_aw); float* part = sym(g_part);

    // --- prep: weight transposes + link-W powers ---
    k_wrzT<<<256, 256>>>(reset_W, reset_b, upd_W, upd_b, WrzT, brz);
    k_t128<<<128, 128>>>(link_W, linkWT);
    k_transWT<<<128, 256>>>(trans_W, transWT);
    k_t128<<<128, 128>>>(att_W1, attW1T);
    k_t128<<<128, 128>>>(out_W, outWT);
    k_mm128<<<128, 128>>>(link_W, link_W, W2);
    k_mm128<<<128, 128>>>(W2, link_W, W3);
    k_t128<<<128, 128>>>(W3, W3T);
    k_beff<<<16, 256>>>(link_b, link_W, W2, beff);

    // edge_states output: e3 = e0 @ W3 + beff
    gemm_h<1, false, false><<<dim3(1, (Bb * Ee) / 128, 1), 512>>>(
        edge_in, nullptr, 128, 0, W3T, 128, 0, beff,
        out_edge, 0, 0, nullptr, nullptr, nullptr, nullptr, 128);

    // F0 = A @ edge_init (batched, split-K x2, B transposed in staging) + rowsum(A)
    gemm_h<0, false, true><<<dim3(2, Nn / 128, Bb), 512>>>(
        Amat, nullptr, Ee, (long long)Nn * Ee,
        edge_in, Dd, (long long)Ee * Dd, nullptr,
        split, (long long)Nn * 128, (long long)MROWS * 128,
        nullptr, nullptr, nullptr, rAp, Ee / 2);
    k_combine<<<(MROWS * 128) / 256, 256>>>(split, F, rAp, rA);

    // --- 3 GRU steps ---
    const float* prop_cur = prop_in;
    for (int s = 0; s < NSTEP; s++) {
        // a_cur = F @ link_W + rA*link_b (in-place)
        gemm_h<2, false, false><<<dim3(1, MROWS / 128, 1), 512>>>(
            F, nullptr, 128, 0, linkWT, 128, 0, link_b,
            F, 0, 0, nullptr, rA, nullptr, nullptr, 128);
        // [r|z] = sigmoid([a_cur|prop] @ Wrz + brz): bx0 -> rp=r*prop, bx1 -> zbuf
        gemm_h<3, true, false><<<dim3(2, MROWS / 128, 1), 512>>>(
            F, prop_cur, 128, 0, WrzT, 256, 0, brz,
            zbuf, 0, 0, rp, nullptr, prop_cur, nullptr, 256);
        // h = tanh([a_cur|rp] @ trans_W + b); prop = p + z*(h-p)
        gemm_h<4, true, false><<<dim3(1, MROWS / 128, 1), 512>>>(
            F, rp, 128, 0, transWT, 256, 0, trans_b,
            prop, 0, 0, nullptr, zbuf, prop_cur, nullptr, 256);
        prop_cur = prop;
    }

    // --- attention pooling epilogue ---
    gemm_h<5, false, false><<<dim3(1, MROWS / 128, 1), 512>>>(
        prop, nullptr, 128, 0, attW1T, 128, 0, att_b1,
        t1, 0, 0, nullptr, nullptr, nullptr, nullptr, 128);
    k_att_score<<<(Bb * Nn) / 8, 256>>>(t1, att_W2, att_b2, att);
    k_softmax<<<Bb, Nn>>>(att, aw);
    gemm_h<5, false, false><<<dim3(1, MROWS / 128, 1), 512>>>(
        prop, nullptr, 128, 0, outWT, 128, 0, out_b,
        outn, 0, 0, nullptr, nullptr, nullptr, nullptr, 128);
    k_residual_part<<<dim3(20, Bb), Dd>>>(prop_in, edge_in, part);
    k_final<<<Bb, Dd>>>(aw, outn, part, out_res, out_mul);
}

// round 6
// speedup vs baseline: 4.5617x; 1.1093x over previous
#include <cuda_runtime.h>
#include <cuda_fp16.h>
#include <math.h>
#include <stdint.h>

#define Bb 32
#define Nn 512
#define Ee 2048
#define Dd 128
#define NSTEP 3
#define MROWS (Bb*Nn)          // 16384

// ---------------- scratch (device globals: allocation-free) ----------------
__device__ float g_G0   [MROWS*Dd];     // A @ edge_init (loop-invariant)
__device__ float g_prop [MROWS*Dd];
__device__ float g_rp   [MROWS*Dd];
__device__ float g_zbuf [MROWS*Dd];
__device__ float g_outn [MROWS*Dd];
__device__ float g_rA   [MROWS];
__device__ float g_WrzTs[3*256*256];    // per-step folded [N=256][K=256]
__device__ float g_TTs  [3*Dd*256];     // per-step folded [N=128][K=256]
__device__ float g_betarz[3*256];
__device__ float g_betah [3*Dd];
__device__ float g_brz  [256];
__device__ float g_attW1T[Dd*Dd];
__device__ float g_outWT [Dd*Dd];
__device__ float g_W2   [Dd*Dd];
__device__ float g_W3   [Dd*Dd];
__device__ float g_W3T  [Dd*Dd];
__device__ float g_c    [3*Dd];         // c1, c2, c3 (bias propagation vectors)
__device__ float g_att  [Bb*Nn];
__device__ float g_aw   [Bb*Nn];
__device__ float g_part [Bb*20*Dd];

// ---------------- fp16 mma helpers ------------------------------------------
__device__ __forceinline__ uint32_t packh2(float x, float y) {
    __half2 h = __floats2half2_rn(x, y);
    return *(uint32_t*)&h;
}
__device__ __forceinline__ void mma_f16(float* c, const uint32_t* a, const uint32_t* b) {
    asm volatile("mma.sync.aligned.m16n8k16.row.col.f32.f16.f16.f32 "
                 "{%0,%1,%2,%3},{%4,%5,%6,%7},{%8,%9},{%0,%1,%2,%3};"
                 : "+f"(c[0]), "+f"(c[1]), "+f"(c[2]), "+f"(c[3])
                 : "r"(a[0]), "r"(a[1]), "r"(a[2]), "r"(a[3]),
                   "r"(b[0]), "r"(b[1]));
}

#define LDW 20   // smem row stride in words

// ---------------- fp16 HMMA GEMM, 128x128 tile, BK=32, double-buffered -----
// A [M,K] row-major fp32; B [N,K] row-major fp32 (or TRANSB: [K,N]).
// EPI: 0=plain + full rowsum(A) -> rAout
//      1=+bias
//      3=rz folded: sigmoid(v + rAv[r]*bias[gcol] + bias2[gcol]); bx0: C2=v*aux2 (rp), bx1: C=v (z)
//      4=hhat folded: h=tanh(v + rAv[r]*bias[col] + bias2[col]); C = p + z*(h-p)
//      5=tanh(+bias)
//      6=fused t1+attention score: v=tanh(v+bias[col]); att[r] = sum_col v*aux1[col] + bias2[0]
template<int EPI, bool SPLITA, bool TRANSB>
__global__ __launch_bounds__(512)
void gemm_h(const float* __restrict__ A, const float* __restrict__ A2, int lda, long long sA,
            const float* __restrict__ Bm, int ldb, long long sB,
            const float* __restrict__ bias, const float* __restrict__ bias2,
            float* __restrict__ C, long long sC,
            float* __restrict__ C2,
            const float* __restrict__ aux1, const float* __restrict__ aux2,
            const float* __restrict__ rAv, float* __restrict__ rAout,
            int Klen)
{
    __shared__ uint32_t As[2][128 * LDW];
    __shared__ uint32_t Bs[2][128 * LDW];
    __shared__ float attp[4][132];

    const int tid  = threadIdx.x;
    const int warp = tid >> 5, lane = tid & 31;
    const int wm = warp & 3, wn = warp >> 2;      // 4x4 warp grid, 32x32 tiles
    const int group = lane >> 2, tig = lane & 3;

    const int  n0g  = (EPI == 3) ? blockIdx.x * 128 : 0;
    const int  m0   = blockIdx.y * 128;
    const long long bz = blockIdx.z;
    A  += bz * sA;
    Bm += bz * sB;
    C  += bz * sC;

    const int ar = tid >> 2, ak2 = (tid & 3) * 4;
    const int tk2 = tid & 15, tnb = (tid >> 4) * 4;

    float acc[2][4][4];
#pragma unroll
    for (int i = 0; i < 2; i++)
#pragma unroll
        for (int j = 0; j < 4; j++)
#pragma unroll
            for (int q = 0; q < 4; q++) acc[i][j][q] = 0.f;

    float rsum = 0.f;
    float4 a0, a1, b0, b1;

    auto loadRegs = [&](int it) {
        const int k0 = it * 32;
        const float* asrc = (SPLITA && it * 32 >= 128)
            ? (A2 + (size_t)(m0 + ar) * 128 + (it * 32 - 128) + ak2 * 2)
            : (A  + (size_t)(m0 + ar) * lda + k0 + ak2 * 2);
        a0 = *(const float4*)asrc;
        a1 = *(const float4*)(asrc + 4);
        if (EPI == 0)
            rsum += ((a0.x + a0.y) + (a0.z + a0.w)) + ((a1.x + a1.y) + (a1.z + a1.w));
        if (!TRANSB) {
            const float* bsrc = Bm + (size_t)(n0g + ar) * ldb + k0 + ak2 * 2;
            b0 = *(const float4*)bsrc;
            b1 = *(const float4*)(bsrc + 4);
        } else {
            const float* bsrc = Bm + (size_t)(k0 + 2 * tk2) * ldb + tnb;
            b0 = *(const float4*)bsrc;
            b1 = *(const float4*)(bsrc + ldb);
        }
    };

    auto stage = [&](int buf) {
        uint4 aw = { packh2(a0.x, a0.y), packh2(a0.z, a0.w),
                     packh2(a1.x, a1.y), packh2(a1.z, a1.w) };
        *(uint4*)&As[buf][ar * LDW + ak2] = aw;
        if (!TRANSB) {
            uint4 bw = { packh2(b0.x, b0.y), packh2(b0.z, b0.w),
                         packh2(b1.x, b1.y), packh2(b1.z, b1.w) };
            *(uint4*)&Bs[buf][ar * LDW + ak2] = bw;
        } else {
            Bs[buf][(tnb + 0) * LDW + tk2] = packh2(b0.x, b1.x);
            Bs[buf][(tnb + 1) * LDW + tk2] = packh2(b0.y, b1.y);
            Bs[buf][(tnb + 2) * LDW + tk2] = packh2(b0.z, b1.z);
            Bs[buf][(tnb + 3) * LDW + tk2] = packh2(b0.w, b1.w);
        }
    };

    const int niter = Klen / 32;
    loadRegs(0);
    stage(0);
    __syncthreads();

    for (int it = 0; it < niter; it++) {
        const int buf = it & 1;
        if (it + 1 < niter) loadRegs(it + 1);

#pragma unroll
        for (int s = 0; s < 2; s++) {
            const int kb = s * 8;
            uint32_t af[2][4], bf[4][2];
#pragma unroll
            for (int mi = 0; mi < 2; mi++) {
                const int m = wm * 32 + mi * 16;
                af[mi][0] = As[buf][(m + group) * LDW + kb + tig];
                af[mi][1] = As[buf][(m + group + 8) * LDW + kb + tig];
                af[mi][2] = As[buf][(m + group) * LDW + kb + tig + 4];
                af[mi][3] = As[buf][(m + group + 8) * LDW + kb + tig + 4];
            }
#pragma unroll
            for (int ni = 0; ni < 4; ni++) {
                const int n = wn * 32 + ni * 8;
                bf[ni][0] = Bs[buf][(n + group) * LDW + kb + tig];
                bf[ni][1] = Bs[buf][(n + group) * LDW + kb + tig + 4];
            }
#pragma unroll
            for (int mi = 0; mi < 2; mi++)
#pragma unroll
                for (int ni = 0; ni < 4; ni++)
                    mma_f16(acc[mi][ni], af[mi], bf[ni]);
        }

        if (it + 1 < niter) stage((it + 1) & 1);
        __syncthreads();
    }

    // full rowsum(A) (EPI0): quad reduce across (tid&3)
    if (EPI == 0) {
        float s = rsum;
        s += __shfl_xor_sync(0xffffffffu, s, 1);
        s += __shfl_xor_sync(0xffffffffu, s, 2);
        if ((tid & 3) == 0)
            rAout[bz * Nn + m0 + ar] = s;
    }

    if (EPI == 6) {
        // fused attention score: per-thread row partials, then tree reduce
        float p[4] = {0.f, 0.f, 0.f, 0.f};
#pragma unroll
        for (int mi = 0; mi < 2; mi++)
#pragma unroll
            for (int ni = 0; ni < 4; ni++) {
                const int cl = wn * 32 + ni * 8 + 2 * tig;
#pragma unroll
                for (int rr = 0; rr < 2; rr++)
#pragma unroll
                    for (int cc = 0; cc < 2; cc++) {
                        const int col = cl + cc;
                        const float v = tanhf(acc[mi][ni][rr * 2 + cc] + bias[col]);
                        p[mi * 2 + rr] += v * aux1[col];
                    }
            }
#pragma unroll
        for (int i = 0; i < 4; i++) {
            p[i] += __shfl_xor_sync(0xffffffffu, p[i], 1);
            p[i] += __shfl_xor_sync(0xffffffffu, p[i], 2);
        }
        if (tig == 0) {
#pragma unroll
            for (int mi = 0; mi < 2; mi++)
#pragma unroll
                for (int rr = 0; rr < 2; rr++)
                    attp[wn][wm * 32 + mi * 16 + group + rr * 8] = p[mi * 2 + rr];
        }
        __syncthreads();
        if (tid < 128)
            C[m0 + tid] = ((attp[0][tid] + attp[1][tid]) +
                           (attp[2][tid] + attp[3][tid])) + bias2[0];
        return;
    }

    // ---- standard epilogues ----
#pragma unroll
    for (int mi = 0; mi < 2; mi++) {
#pragma unroll
        for (int ni = 0; ni < 4; ni++) {
            const int cl = wn * 32 + ni * 8 + 2 * tig;
#pragma unroll
            for (int rr = 0; rr < 2; rr++) {
                const long long r = m0 + wm * 32 + mi * 16 + group + rr * 8;
#pragma unroll
                for (int cc = 0; cc < 2; cc++) {
                    float v = acc[mi][ni][rr * 2 + cc];
                    const int col  = cl + cc;
                    const int gcol = n0g + col;
                    if (EPI == 0) {
                        C[r * 128 + col] = v;
                    } else if (EPI == 1) {
                        C[r * 128 + col] = v + bias[col];
                    } else if (EPI == 3) {
                        v = 1.f / (1.f + __expf(-(v + rAv[r] * bias[gcol] + bias2[gcol])));
                        if (blockIdx.x == 0) C2[r * 128 + col] = v * aux2[r * 128 + col];
                        else                 C [r * 128 + col] = v;
                    } else if (EPI == 4) {
                        const float h = tanhf(v + rAv[r] * bias[col] + bias2[col]);
                        const float z = aux1[r * 128 + col];
                        const float p = aux2[r * 128 + col];
                        C[r * 128 + col] = fmaf(z, h - p, p);
                    } else { // 5
                        C[r * 128 + col] = tanhf(v + bias[col]);
                    }
                }
            }
        }
    }
}

// ---------------- prep kernels ------------------------------------------------
// C[r][c] = sum_k A[r][k] B[k][c], 128^3 fp32
__global__ void k_mm128(const float* __restrict__ A, const float* __restrict__ B,
                        float* __restrict__ C) {
    const int r = blockIdx.x, c = threadIdx.x;
    __shared__ float sA[128];
    sA[c] = A[r * 128 + c];
    __syncthreads();
    float s0 = 0.f, s1 = 0.f, s2 = 0.f, s3 = 0.f;
#pragma unroll
    for (int k = 0; k < 128; k += 4) {
        s0 = fmaf(sA[k + 0], B[(k + 0) * 128 + c], s0);
        s1 = fmaf(sA[k + 1], B[(k + 1) * 128 + c], s1);
        s2 = fmaf(sA[k + 2], B[(k + 2) * 128 + c], s2);
        s3 = fmaf(sA[k + 3], B[(k + 3) * 128 + c], s3);
    }
    C[r * 128 + c] = (s0 + s1) + (s2 + s3);
}

// c1 = b ; c2 = b + b@W ; c3 = b + b@W + b@W2.   warp per column.
__global__ void k_cvec(const float* __restrict__ b, const float* __restrict__ W,
                       const float* __restrict__ W2, float* __restrict__ c) {
    const int col  = blockIdx.x * 8 + (threadIdx.x >> 5);
    const int lane = threadIdx.x & 31;
    float sw = 0.f, sw2 = 0.f;
#pragma unroll
    for (int k = lane; k < 128; k += 32) {
        const float bk = b[k];
        sw  = fmaf(bk, W [k * 128 + col], sw);
        sw2 = fmaf(bk, W2[k * 128 + col], sw2);
    }
#pragma unroll
    for (int o = 16; o; o >>= 1) {
        sw  += __shfl_xor_sync(0xffffffffu, sw, o);
        sw2 += __shfl_xor_sync(0xffffffffu, sw2, o);
    }
    if (lane == 0) {
        const float bc = b[col];
        c[col]       = bc;
        c[128 + col] = bc + sw;
        c[256 + col] = bc + sw + sw2;
    }
}

// One launch: all folded weights, transposes, beta vectors, brz.
__global__ void k_fold(const float* __restrict__ W1, const float* __restrict__ W2,
                       const float* __restrict__ W3,
                       const float* __restrict__ rW, const float* __restrict__ uW,
                       const float* __restrict__ rb, const float* __restrict__ ub,
                       const float* __restrict__ tW,
                       const float* __restrict__ attW1, const float* __restrict__ outW,
                       const float* __restrict__ cvec,
                       float* __restrict__ WrzTs, float* __restrict__ TTs,
                       float* __restrict__ W3T, float* __restrict__ attW1T,
                       float* __restrict__ outWT,
                       float* __restrict__ betarz, float* __restrict__ betah,
                       float* __restrict__ brz) {
    const int x = blockIdx.x, y = blockIdx.y, tid = threadIdx.x;
    const float* Wpow[3] = { W1, W2, W3 };

    auto wrz = [&](int j, int n) -> float {
        return (n < 128) ? rW[j * 128 + n] : uW[j * 128 + (n - 128)];
    };

    if (y < 3) {                       // WrzTs[s] folded half: k'=x, n=tid
        const float* Ws = Wpow[y];
        float s = 0.f;
#pragma unroll 4
        for (int j = 0; j < 128; j++) s = fmaf(Ws[x * 128 + j], wrz(j, tid), s);
        WrzTs[(size_t)y * 65536 + tid * 256 + x] = s;
    } else if (y < 6) {                // WrzTs[s] bottom half: k=128+x, n=tid
        WrzTs[(size_t)(y - 3) * 65536 + tid * 256 + 128 + x] = wrz(128 + x, tid);
    } else if (y < 9) {                // TTs[s] folded: k'=x, n=tid<128
        if (tid < 128) {
            const float* Ws = Wpow[y - 6];
            float s = 0.f;
#pragma unroll 4
            for (int j = 0; j < 128; j++) s = fmaf(Ws[x * 128 + j], tW[j * 128 + tid], s);
            TTs[(size_t)(y - 6) * 32768 + tid * 256 + x] = s;
        }
    } else if (y < 12) {               // TTs[s] bottom: k=128+x
        if (tid < 128)
            TTs[(size_t)(y - 9) * 32768 + tid * 256 + 128 + x] = tW[(128 + x) * 128 + tid];
    } else if (y == 12) {
        if (tid < 128) W3T[tid * 128 + x] = W3[x * 128 + tid];
    } else if (y == 13) {
        if (tid < 128) attW1T[tid * 128 + x] = attW1[x * 128 + tid];
    } else if (y == 14) {
        if (tid < 128) outWT[tid * 128 + x] = outW[x * 128 + tid];
    } else {                           // y == 15: betas + brz
        if (x < 3) {
            const float* c = cvec + x * 128;
            float s = 0.f;
#pragma unroll 4
            for (int j = 0; j < 128; j++) s = fmaf(c[j], wrz(j, tid), s);
            betarz[x * 256 + tid] = s;
            if (tid < 128) {
                float h = 0.f;
#pragma unroll 4
                for (int j = 0; j < 128; j++) h = fmaf(c[j], tW[j * 128 + tid], h);
                betah[x * 128 + tid] = h;
            }
        } else if (x == 3) {
            brz[tid] = (tid < 128) ? rb[tid] : ub[tid - 128];
        }
    }
}

// ---------------- misc kernels -------------------------------------------------
__global__ void k_softmax(const float* __restrict__ att, float* __restrict__ aw) {
    const int b = blockIdx.x;
    const int n = threadIdx.x;              // 512
    __shared__ float red[Nn];
    const float v = att[b * Nn + n];
    red[n] = v;
    __syncthreads();
    for (int s = 256; s; s >>= 1) { if (n < s) red[n] = fmaxf(red[n], red[n + s]); __syncthreads(); }
    const float m = red[0];
    __syncthreads();
    const float e = __expf(v - m);
    red[n] = e;
    __syncthreads();
    for (int s = 256; s; s >>= 1) { if (n < s) red[n] += red[n + s]; __syncthreads(); }
    aw[b * Nn + n] = e / red[0];
}
__global__ void k_residual_part(const float* __restrict__ prop0, const float* __restrict__ edge0,
                                float* __restrict__ part) {
    const int ch = blockIdx.x, b = blockIdx.y, d = threadIdx.x;
    float s = 0.f;
    const int r0 = ch * 128;
#pragma unroll 4
    for (int r = r0; r < r0 + 128; r++) {
        if (r < Nn) s += prop0[((long long)b * Nn + r) * Dd + d];
        else        s += edge0[((long long)b * Ee + (r - Nn)) * Dd + d];
    }
    part[(b * 20 + ch) * Dd + d] = s;
}
__global__ void k_final(const float* __restrict__ aw, const float* __restrict__ outn,
                        const float* __restrict__ part,
                        float* __restrict__ d_res, float* __restrict__ d_mul) {
    const int b = blockIdx.x, d = threadIdx.x;
    __shared__ float saw[Nn];
    for (int n = threadIdx.x; n < Nn; n += 128) saw[n] = aw[b * Nn + n];
    __syncthreads();
    const float* ob = outn + (long long)b * Nn * Dd;
    float acc = 0.f;
#pragma unroll 8
    for (int n = 0; n < Nn; n++) acc = fmaf(saw[n], ob[n * Dd + d], acc);
    float resid = 0.f;
#pragma unroll
    for (int c = 0; c < 20; c++) resid += part[(b * 20 + c) * Dd + d];
    resid *= (1.f / 2560.f);
    d_mul[b * Dd + d] = acc;
    d_res[b * Dd + d] = fmaxf(tanhf(acc) + resid, 0.f);
}

// ---------------- host launch ----------------------------------------------------
static float* sym(const void* s) { void* p = nullptr; cudaGetSymbolAddress(&p, s); return (float*)p; }

extern "C" void kernel_launch(void* const* d_in, const int* in_sizes, int n_in,
                              void* d_out, int out_size) {
    const float* prop_in = (const float*)d_in[0];
    const float* edge_in = (const float*)d_in[1];
    const float* Amat    = (const float*)d_in[2];
    const float* link_W  = (const float*)d_in[4];
    const float* link_b  = (const float*)d_in[5];
    const float* reset_W = (const float*)d_in[6];
    const float* reset_b = (const float*)d_in[7];
    const float* upd_W   = (const float*)d_in[8];
    const float* upd_b   = (const float*)d_in[9];
    const float* trans_W = (const float*)d_in[10];
    const float* trans_b = (const float*)d_in[11];
    const float* att_W1  = (const float*)d_in[12];
    const float* att_b1  = (const float*)d_in[13];
    const float* att_W2  = (const float*)d_in[14];
    const float* att_b2  = (const float*)d_in[15];
    const float* out_W   = (const float*)d_in[16];
    const float* out_b   = (const float*)d_in[17];

    float* out      = (float*)d_out;
    float* out_res  = out;
    float* out_mul  = out + Bb * Dd;
    float* out_edge = out + 2 * Bb * Dd;

    float* G0 = sym(g_G0); float* prop = sym(g_prop); float* rp = sym(g_rp);
    float* zbuf = sym(g_zbuf); float* outn = sym(g_outn); float* rA = sym(g_rA);
    float* WrzTs = sym(g_WrzTs); float* TTs = sym(g_TTs);
    float* betarz = sym(g_betarz); float* betah = sym(g_betah); float* brz = sym(g_brz);
    float* attW1T = sym(g_attW1T); float* outWT = sym(g_outWT);
    float* W2 = sym(g_W2); float* W3 = sym(g_W3); float* W3T = sym(g_W3T);
    float* cvec = sym(g_c);
    float* att = sym(g_att); float* aw = sym(g_aw); float* part = sym(g_part);

    // --- prep: link-W powers, bias vectors, folded weights (4 launches) ---
    k_mm128<<<128, 128>>>(link_W, link_W, W2);
    k_mm128<<<128, 128>>>(W2, link_W, W3);
    k_cvec<<<16, 256>>>(link_b, link_W, W2, cvec);
    k_fold<<<dim3(128, 16), 256>>>(link_W, W2, W3, reset_W, upd_W, reset_b, upd_b,
                                   trans_W, att_W1, out_W, cvec,
                                   WrzTs, TTs, W3T, attW1T, outWT,
                                   betarz, betah, brz);

    // edge_states output: e3 = e0 @ W3 + c3
    gemm_h<1, false, false><<<dim3(1, (Bb * Ee) / 128, 1), 512>>>(
        edge_in, nullptr, 128, 0, W3T, 128, 0, cvec + 256, nullptr,
        out_edge, 0, nullptr, nullptr, nullptr, nullptr, nullptr, 128);

    // G0 = A @ edge_init (batched, full K=1024, B transposed in staging) + rowsum(A)
    gemm_h<0, false, true><<<dim3(1, Nn / 128, Bb), 512>>>(
        Amat, nullptr, Ee, (long long)Nn * Ee,
        edge_in, Dd, (long long)Ee * Dd, nullptr, nullptr,
        G0, (long long)Nn * 128, nullptr, nullptr, nullptr, nullptr, rA, Ee);

    // --- 3 GRU steps (2 GEMMs each, a_cur folded away) ---
    const float* prop_cur = prop_in;
    for (int s = 0; s < NSTEP; s++) {
        // [r|z] = sigmoid([G0|prop] @ WrzTs[s] + rA*betarz[s] + brz)
        gemm_h<3, true, false><<<dim3(2, MROWS / 128, 1), 512>>>(
            G0, prop_cur, 128, 0, WrzTs + (size_t)s * 65536, 256, 0,
            betarz + s * 256, brz,
            zbuf, 0, rp, nullptr, prop_cur, rA, nullptr, 256);
        // h = tanh([G0|rp] @ TTs[s] + rA*betah[s] + trans_b); prop = p + z*(h-p)
        gemm_h<4, true, false><<<dim3(1, MROWS / 128, 1), 512>>>(
            G0, rp, 128, 0, TTs + (size_t)s * 32768, 256, 0,
            betah + s * 128, trans_b,
            prop, 0, nullptr, zbuf, prop_cur, rA, nullptr, 256);
        prop_cur = prop;
    }

    // --- attention pooling: fused tanh(prop@W1+b1)@W2+b2 in one GEMM epilogue ---
    gemm_h<6, false, false><<<dim3(1, MROWS / 128, 1), 512>>>(
        prop, nullptr, 128, 0, attW1T, 128, 0, att_b1, att_b2,
        att, 0, nullptr, att_W2, nullptr, nullptr, nullptr, 128);
    k_softmax<<<Bb, Nn>>>(att, aw);
    gemm_h<5, false, false><<<dim3(1, MROWS / 128, 1), 512>>>(
        prop, nullptr, 128, 0, outWT, 128, 0, out_b, nullptr,
        outn, 0, nullptr, nullptr, nullptr, nullptr, nullptr, 128);
    k_residual_part<<<dim3(20, Bb), Dd>>>(prop_in, edge_in, part);
    k_final<<<Bb, Dd>>>(aw, outn, part, out_res, out_mul);
}